// round 10
// baseline (speedup 1.0000x reference)
#include <cuda_runtime.h>
#include <math.h>

#define BOUND 10.0f
#define EPSF  1e-6f
#define MIN_SCALE 1e-4f

#define MAXD 1024
#define K64  64
#define CELLS 256
#define CELLS_PER_UNIT (256.0f / 20.0f)   // 12.8

// Precomputed packed spline tables (scratch; allocation-free per harness rules)
__device__ float4 g_P0[MAXD * K64];       // {x0, 1/w, y0, h}
__device__ float2 g_P1[MAXD * K64];       // {d0, d0 + d1 - 2*s}
__device__ unsigned int g_tab[MAXD * (CELLS / 4)];  // 4 packed u8 lower-bound idx per cell
__device__ float g_scale[MAXD];

__device__ __forceinline__ float softplusf(float x) {
    return (x > 20.0f) ? x : log1pf(__expf(x));
}

// One block per dim, 64 threads. softmax -> scan -> knots -> packed params + cell table.
__global__ void spline_preproc_kernel(const float* __restrict__ raw_w,
                                      const float* __restrict__ raw_h,
                                      const float* __restrict__ raw_s,
                                      const float* __restrict__ log_scale) {
    const int d = blockIdx.x;
    const int t = threadIdx.x;          // 0..63
    const int lane = t & 31, wid = t >> 5;

    __shared__ float sxk[K64 + 1], syk[K64 + 1], ssl[K64 + 1];
    __shared__ float sred[K64];
    __shared__ float s2[4];

    // ---- widths softmax ----
    float xw = raw_w[d * K64 + t];
    float m = xw;
    #pragma unroll
    for (int off = 16; off > 0; off >>= 1) m = fmaxf(m, __shfl_xor_sync(0xffffffff, m, off));
    if (lane == 0) s2[wid] = m;
    __syncthreads();
    m = fmaxf(s2[0], s2[1]);
    float ew = __expf(xw - m);
    float sm = ew;
    #pragma unroll
    for (int off = 16; off > 0; off >>= 1) sm += __shfl_xor_sync(0xffffffff, sm, off);
    if (lane == 0) s2[2 + wid] = sm;
    __syncthreads();
    float wsum = s2[2] + s2[3];
    float ww = ew * (2.0f * BOUND) / wsum;

    // inclusive scan of widths
    float v = ww;
    #pragma unroll
    for (int off = 1; off < K64; off <<= 1) {
        sred[t] = v; __syncthreads();
        if (t >= off) v += sred[t - off];
        __syncthreads();
    }
    sxk[t + 1] = v - BOUND;
    if (t == 0) sxk[0] = -BOUND;
    __syncthreads();

    // ---- heights softmax ----
    float xh = raw_h[d * K64 + t];
    float mh = xh;
    #pragma unroll
    for (int off = 16; off > 0; off >>= 1) mh = fmaxf(mh, __shfl_xor_sync(0xffffffff, mh, off));
    if (lane == 0) s2[wid] = mh;
    __syncthreads();
    mh = fmaxf(s2[0], s2[1]);
    float eh = __expf(xh - mh);
    float sh2 = eh;
    #pragma unroll
    for (int off = 16; off > 0; off >>= 1) sh2 += __shfl_xor_sync(0xffffffff, sh2, off);
    if (lane == 0) s2[2 + wid] = sh2;
    __syncthreads();
    float hsum = s2[2] + s2[3];
    float hh = eh * (2.0f * BOUND) / hsum;

    float vh = hh;
    #pragma unroll
    for (int off = 1; off < K64; off <<= 1) {
        sred[t] = vh; __syncthreads();
        if (t >= off) vh += sred[t - off];
        __syncthreads();
    }
    syk[t + 1] = vh - BOUND;
    if (t == 0) syk[0] = -BOUND;

    // ---- slopes ----
    ssl[t] = softplusf(raw_s[d * (K64 + 1) + t]);
    if (t == 0) {
        ssl[K64] = softplusf(raw_s[d * (K64 + 1) + K64]);
        g_scale[d] = softplusf(log_scale[d]) + MIN_SCALE;
    }
    __syncthreads();

    // ---- pack per-interval params ----
    {
        float x0 = sxk[t], y0 = syk[t];
        float inv_w = 1.0f / ww;
        float s = hh / ww;
        float dk0 = ssl[t], dk1 = ssl[t + 1];
        g_P0[d * K64 + t] = make_float4(x0, inv_w, y0, hh);
        g_P1[d * K64 + t] = make_float2(dk0, dk0 + dk1 - 2.0f * s);
    }

    // ---- cell table: lower-bound interval index for each cell's left edge ----
    {
        unsigned int packed = 0;
        #pragma unroll
        for (int j = 0; j < 4; j++) {
            int c = t * 4 + j;
            float left = -BOUND + (float)c * (20.0f / (float)CELLS);
            int idx = 0;
            #pragma unroll
            for (int st = 32; st > 0; st >>= 1) {
                int cand = idx + st;
                if (cand <= K64 - 1 && sxk[cand] <= left) idx = cand;
            }
            packed |= ((unsigned int)idx) << (8 * j);
        }
        g_tab[d * (CELLS / 4) + t] = packed;
    }
}

// Main kernel: DTILE=16 dims/block. Each thread owns 4 CONSECUTIVE dims
// (laned = tid&3 -> 16B float4 chunk of u/out), rgrp = tid>>2 -> 64 rows per
// block iteration.
//
// Smem swizzle: entry k of local dim d stored at slot (k + (d>>2)) & 63 so
// LDS.128/LDS.64/probe phases are conflict-free.
//
// Search: u8 cell table lower bound + 2 BRANCHLESS predicated steps + a
// rarely-entered cleanup loop (avoids warp-max while-loop cost).
#define DTILE 16
#define TPB   256
#define STRD  65           // padded per-dim stride (entries)
#define TABSTRD 260        // padded tab stride (bytes)
#define GRIDY 13           // 64*13=832 blocks, single wave at 6 blocks/SM

__global__ void __launch_bounds__(TPB)
rqs_main_kernel(const float* __restrict__ u,
                const float* __restrict__ tau,
                const float* __restrict__ bias,
                float* __restrict__ out,
                int B, int D) {
    __shared__ float4 sP0[DTILE * STRD];            // 16640 B
    __shared__ float2 sP1[DTILE * STRD];            //  8320 B
    __shared__ float  sXK[DTILE * STRD];            //  4160 B
    __shared__ unsigned char sTab[DTILE * TABSTRD]; //  4160 B
    __shared__ float sScale[DTILE], sBias[DTILE];

    const int d0 = blockIdx.x * DTILE;

    // Stage tables with the additive swizzle.
    for (int i = threadIdx.x; i < DTILE * K64; i += TPB) {
        const int dim = i >> 6, k = i & 63;
        const int kp = (k + (dim >> 2)) & 63;       // swizzled slot
        const float4 p = g_P0[d0 * K64 + i];
        sP0[dim * STRD + kp] = p;
        sXK[dim * STRD + kp] = p.x;
        sP1[dim * STRD + kp] = g_P1[d0 * K64 + i];
    }
    for (int i = threadIdx.x; i < DTILE * (CELLS / 4); i += TPB) {
        const int dim = i >> 6, j = i & 63;
        *(unsigned int*)(sTab + dim * TABSTRD + 4 * j) = g_tab[d0 * (CELLS / 4) + i];
    }
    if (threadIdx.x < DTILE) {
        sScale[threadIdx.x] = g_scale[d0 + threadIdx.x];
        sBias[threadIdx.x]  = bias[d0 + threadIdx.x];
    }
    __syncthreads();

    const int laned = threadIdx.x & 3;               // 0..3: which float4 chunk
    const int rgrp  = threadIdx.x >> 2;              // 0..63: row group
    const int dbase = 4 * laned;                     // local dim base (0,4,8,12)

    const float sc0 = sScale[dbase + 0], sc1 = sScale[dbase + 1],
                sc2 = sScale[dbase + 2], sc3 = sScale[dbase + 3];
    const float bi0 = sBias[dbase + 0], bi1 = sBias[dbase + 1],
                bi2 = sBias[dbase + 2], bi3 = sBias[dbase + 3];

    const int rowsPerIter = TPB / 4;                 // 64
    const int rstride = gridDim.y * rowsPerIter;

    for (int r = blockIdx.y * rowsPerIter + rgrp; r < B; r += rstride) {
        const float4 u4 = *(const float4*)(u + (size_t)r * D + d0 + dbase);
        const float tv = __ldg(tau + r);

        float zz[4];
        {
            const float ua[4] = {u4.x, u4.y, u4.z, u4.w};
            #pragma unroll
            for (int jj = 0; jj < 4; jj++) {
                const float us = fminf(fmaxf(ua[jj], EPSF), 1.0f - EPSF);
                zz[jj] = __logf(__fdividef(us, 1.0f - us));
            }
        }

        // cell index (single fmaf) + clamp
        int idx[4];
        #pragma unroll
        for (int jj = 0; jj < 4; jj++) {
            int c = (int)fmaf(zz[jj], CELLS_PER_UNIT, (float)(CELLS / 2));
            c = max(0, min(CELLS - 1, c));
            idx[jj] = sTab[(dbase + jj) * TABSTRD + c];
        }

        // 2 branchless refinement steps per chain
        #pragma unroll
        for (int jj = 0; jj < 4; jj++) {
            const float* xs = sXK + (dbase + jj) * STRD;
            int i0 = idx[jj];
            i0 += (i0 < K64 - 1 && xs[(i0 + 1 + laned) & 63] <= zz[jj]) ? 1 : 0;
            i0 += (i0 < K64 - 1 && xs[(i0 + 1 + laned) & 63] <= zz[jj]) ? 1 : 0;
            idx[jj] = i0;
        }
        // rare cleanup (uniformly not-taken for most warps)
        #pragma unroll
        for (int jj = 0; jj < 4; jj++) {
            const float* xs = sXK + (dbase + jj) * STRD;
            while (idx[jj] < K64 - 1 && xs[(idx[jj] + 1 + laned) & 63] <= zz[jj]) idx[jj]++;
        }

        float res[4];
        #pragma unroll
        for (int jj = 0; jj < 4; jj++) {
            const float z = zz[jj];
            if (z > -BOUND && z < BOUND) {
                const int kp = (idx[jj] + laned) & 63;
                const float4 p = sP0[(dbase + jj) * STRD + kp];  // {x0,1/w,y0,h}
                const float2 q = sP1[(dbase + jj) * STRD + kp];  // {d0,d0+d1-2s}
                const float theta = (z - p.x) * p.y;
                const float t1m = theta * (1.0f - theta);
                const float s = p.w * p.y;                       // h/w
                const float den = fmaf(q.y, t1m, s);
                const float num = fmaf(s * theta, theta, q.x * t1m);
                res[jj] = fmaf(p.w, __fdividef(num, den), p.z);
            } else {
                res[jj] = z;
            }
        }

        float4 o4;
        o4.x = tv * fmaf(res[0], sc0, bi0);
        o4.y = tv * fmaf(res[1], sc1, bi1);
        o4.z = tv * fmaf(res[2], sc2, bi2);
        o4.w = tv * fmaf(res[3], sc3, bi3);
        *(float4*)(out + (size_t)r * D + d0 + dbase) = o4;
    }
}

extern "C" void kernel_launch(void* const* d_in, const int* in_sizes, int n_in,
                              void* d_out, int out_size) {
    const float* u         = (const float*)d_in[0];
    const float* tau       = (const float*)d_in[1];
    const float* log_scale = (const float*)d_in[2];
    const float* bias      = (const float*)d_in[3];
    const float* raw_w     = (const float*)d_in[4];
    const float* raw_h     = (const float*)d_in[5];
    const float* raw_s     = (const float*)d_in[6];
    float* out = (float*)d_out;

    const int D = in_sizes[2];
    const int B = in_sizes[0] / D;

    spline_preproc_kernel<<<D, K64>>>(raw_w, raw_h, raw_s, log_scale);

    dim3 grid(D / DTILE, GRIDY);
    rqs_main_kernel<<<grid, TPB>>>(u, tau, bias, out, B, D);
}

// round 12
// speedup vs baseline: 1.1111x; 1.1111x over previous
#include <cuda_runtime.h>
#include <math.h>

#define BOUND 10.0f
#define EPSF  1e-6f
#define MIN_SCALE 1e-4f

#define MAXD 1024
#define K64  64
#define CELLS 256
#define CELLS_PER_UNIT (256.0f / 20.0f)   // 12.8

// Precomputed packed spline tables (scratch; allocation-free per harness rules)
__device__ float4 g_P0[MAXD * K64];       // {x0, 1/w, y0, h}
__device__ float2 g_P1[MAXD * K64];       // {d0, d0 + d1 - 2*s}
__device__ unsigned int g_tab[MAXD * (CELLS / 4)];  // 4 packed u8 lower-bound idx per cell
__device__ float g_scale[MAXD];

__device__ __forceinline__ float softplusf(float x) {
    return (x > 20.0f) ? x : log1pf(__expf(x));
}

// One block per dim, 64 threads. softmax -> scan -> knots -> packed params + cell table.
__global__ void spline_preproc_kernel(const float* __restrict__ raw_w,
                                      const float* __restrict__ raw_h,
                                      const float* __restrict__ raw_s,
                                      const float* __restrict__ log_scale) {
    const int d = blockIdx.x;
    const int t = threadIdx.x;          // 0..63
    const int lane = t & 31, wid = t >> 5;

    __shared__ float sxk[K64 + 1], syk[K64 + 1], ssl[K64 + 1];
    __shared__ float sred[K64];
    __shared__ float s2[4];

    // ---- widths softmax ----
    float xw = raw_w[d * K64 + t];
    float m = xw;
    #pragma unroll
    for (int off = 16; off > 0; off >>= 1) m = fmaxf(m, __shfl_xor_sync(0xffffffff, m, off));
    if (lane == 0) s2[wid] = m;
    __syncthreads();
    m = fmaxf(s2[0], s2[1]);
    float ew = __expf(xw - m);
    float sm = ew;
    #pragma unroll
    for (int off = 16; off > 0; off >>= 1) sm += __shfl_xor_sync(0xffffffff, sm, off);
    if (lane == 0) s2[2 + wid] = sm;
    __syncthreads();
    float wsum = s2[2] + s2[3];
    float ww = ew * (2.0f * BOUND) / wsum;

    // inclusive scan of widths
    float v = ww;
    #pragma unroll
    for (int off = 1; off < K64; off <<= 1) {
        sred[t] = v; __syncthreads();
        if (t >= off) v += sred[t - off];
        __syncthreads();
    }
    sxk[t + 1] = v - BOUND;
    if (t == 0) sxk[0] = -BOUND;
    __syncthreads();

    // ---- heights softmax ----
    float xh = raw_h[d * K64 + t];
    float mh = xh;
    #pragma unroll
    for (int off = 16; off > 0; off >>= 1) mh = fmaxf(mh, __shfl_xor_sync(0xffffffff, mh, off));
    if (lane == 0) s2[wid] = mh;
    __syncthreads();
    mh = fmaxf(s2[0], s2[1]);
    float eh = __expf(xh - mh);
    float sh2 = eh;
    #pragma unroll
    for (int off = 16; off > 0; off >>= 1) sh2 += __shfl_xor_sync(0xffffffff, sh2, off);
    if (lane == 0) s2[2 + wid] = sh2;
    __syncthreads();
    float hsum = s2[2] + s2[3];
    float hh = eh * (2.0f * BOUND) / hsum;

    float vh = hh;
    #pragma unroll
    for (int off = 1; off < K64; off <<= 1) {
        sred[t] = vh; __syncthreads();
        if (t >= off) vh += sred[t - off];
        __syncthreads();
    }
    syk[t + 1] = vh - BOUND;
    if (t == 0) syk[0] = -BOUND;

    // ---- slopes ----
    ssl[t] = softplusf(raw_s[d * (K64 + 1) + t]);
    if (t == 0) {
        ssl[K64] = softplusf(raw_s[d * (K64 + 1) + K64]);
        g_scale[d] = softplusf(log_scale[d]) + MIN_SCALE;
    }
    __syncthreads();

    // ---- pack per-interval params ----
    {
        float x0 = sxk[t], y0 = syk[t];
        float inv_w = 1.0f / ww;
        float s = hh / ww;
        float dk0 = ssl[t], dk1 = ssl[t + 1];
        g_P0[d * K64 + t] = make_float4(x0, inv_w, y0, hh);
        g_P1[d * K64 + t] = make_float2(dk0, dk0 + dk1 - 2.0f * s);
    }

    // ---- cell table: lower-bound interval index for each cell's left edge ----
    {
        unsigned int packed = 0;
        #pragma unroll
        for (int j = 0; j < 4; j++) {
            int c = t * 4 + j;
            float left = -BOUND + (float)c * (20.0f / (float)CELLS);
            int idx = 0;
            #pragma unroll
            for (int st = 32; st > 0; st >>= 1) {
                int cand = idx + st;
                if (cand <= K64 - 1 && sxk[cand] <= left) idx = cand;
            }
            packed |= ((unsigned int)idx) << (8 * j);
        }
        g_tab[d * (CELLS / 4) + t] = packed;
    }
}

// Main kernel (R8 config + software-pipelined u/tau prefetch).
// DTILE=16 dims/block; each thread owns 4 consecutive dims (float4 chunk);
// rgrp = tid>>2 -> 64 rows/block-iter. Additive smem swizzle keeps
// LDS.128/LDS.64/probe phases conflict-free.
#define DTILE 16
#define TPB   256
#define STRD  65           // padded per-dim stride (entries)
#define TABSTRD 260        // padded tab stride (bytes)
#define GRIDY 11           // 64*11=704 blocks (best-measured config)

__global__ void __launch_bounds__(TPB)
rqs_main_kernel(const float* __restrict__ u,
                const float* __restrict__ tau,
                const float* __restrict__ bias,
                float* __restrict__ out,
                int B, int D) {
    __shared__ float4 sP0[DTILE * STRD];            // 16640 B
    __shared__ float2 sP1[DTILE * STRD];            //  8320 B
    __shared__ float  sXK[DTILE * STRD];            //  4160 B
    __shared__ unsigned char sTab[DTILE * TABSTRD]; //  4160 B
    __shared__ float sScale[DTILE], sBias[DTILE];

    const int d0 = blockIdx.x * DTILE;

    // Stage tables with the additive swizzle.
    for (int i = threadIdx.x; i < DTILE * K64; i += TPB) {
        const int dim = i >> 6, k = i & 63;
        const int kp = (k + (dim >> 2)) & 63;       // swizzled slot
        const float4 p = g_P0[d0 * K64 + i];
        sP0[dim * STRD + kp] = p;
        sXK[dim * STRD + kp] = p.x;
        sP1[dim * STRD + kp] = g_P1[d0 * K64 + i];
    }
    for (int i = threadIdx.x; i < DTILE * (CELLS / 4); i += TPB) {
        const int dim = i >> 6, j = i & 63;
        *(unsigned int*)(sTab + dim * TABSTRD + 4 * j) = g_tab[d0 * (CELLS / 4) + i];
    }
    if (threadIdx.x < DTILE) {
        sScale[threadIdx.x] = g_scale[d0 + threadIdx.x];
        sBias[threadIdx.x]  = bias[d0 + threadIdx.x];
    }
    __syncthreads();

    const int laned = threadIdx.x & 3;               // 0..3: which float4 chunk
    const int rgrp  = threadIdx.x >> 2;              // 0..63: row group
    const int dbase = 4 * laned;                     // local dim base (0,4,8,12)

    const float sc0 = sScale[dbase + 0], sc1 = sScale[dbase + 1],
                sc2 = sScale[dbase + 2], sc3 = sScale[dbase + 3];
    const float bi0 = sBias[dbase + 0], bi1 = sBias[dbase + 1],
                bi2 = sBias[dbase + 2], bi3 = sBias[dbase + 3];

    const int rowsPerIter = TPB / 4;                 // 64
    const int rstride = gridDim.y * rowsPerIter;

    int r = blockIdx.y * rowsPerIter + rgrp;

    // ---- prefetch iteration 0 ----
    float4 u4 = make_float4(0.f, 0.f, 0.f, 0.f);
    float tv = 0.f;
    if (r < B) {
        u4 = *(const float4*)(u + (size_t)r * D + d0 + dbase);
        tv = __ldg(tau + r);
    }

    while (r < B) {
        const int rn = r + rstride;
        // ---- prefetch next iteration's global data (hides LDG latency) ----
        float4 u4n;
        float tvn;
        if (rn < B) {
            u4n = *(const float4*)(u + (size_t)rn * D + d0 + dbase);
            tvn = __ldg(tau + rn);
        }

        float zz[4];
        {
            const float ua[4] = {u4.x, u4.y, u4.z, u4.w};
            #pragma unroll
            for (int jj = 0; jj < 4; jj++) {
                const float us = fminf(fmaxf(ua[jj], EPSF), 1.0f - EPSF);
                zz[jj] = __logf(__fdividef(us, 1.0f - us));
            }
        }

        int idx[4];
        #pragma unroll
        for (int jj = 0; jj < 4; jj++) {
            int c = (int)fmaf(zz[jj], CELLS_PER_UNIT, (float)(CELLS / 2));
            c = max(0, min(CELLS - 1, c));
            idx[jj] = sTab[(dbase + jj) * TABSTRD + c];
        }

        #pragma unroll
        for (int jj = 0; jj < 4; jj++) {
            const float* xs = sXK + (dbase + jj) * STRD;
            int nxt = idx[jj] + 1;
            while (nxt < K64 && xs[(nxt + laned) & 63] <= zz[jj]) { idx[jj] = nxt; ++nxt; }
        }

        float res[4];
        #pragma unroll
        for (int jj = 0; jj < 4; jj++) {
            const float z = zz[jj];
            if (z > -BOUND && z < BOUND) {
                const int kp = (idx[jj] + laned) & 63;
                const float4 p = sP0[(dbase + jj) * STRD + kp];  // {x0,1/w,y0,h}
                const float2 q = sP1[(dbase + jj) * STRD + kp];  // {d0,d0+d1-2s}
                const float theta = (z - p.x) * p.y;
                const float t1m = theta * (1.0f - theta);
                const float s = p.w * p.y;                       // h/w
                const float den = fmaf(q.y, t1m, s);
                const float num = fmaf(s * theta, theta, q.x * t1m);
                res[jj] = fmaf(p.w, __fdividef(num, den), p.z);
            } else {
                res[jj] = z;
            }
        }

        float4 o4;
        o4.x = tv * fmaf(res[0], sc0, bi0);
        o4.y = tv * fmaf(res[1], sc1, bi1);
        o4.z = tv * fmaf(res[2], sc2, bi2);
        o4.w = tv * fmaf(res[3], sc3, bi3);
        *(float4*)(out + (size_t)r * D + d0 + dbase) = o4;

        u4 = u4n;
        tv = tvn;
        r = rn;
    }
}

extern "C" void kernel_launch(void* const* d_in, const int* in_sizes, int n_in,
                              void* d_out, int out_size) {
    const float* u         = (const float*)d_in[0];
    const float* tau       = (const float*)d_in[1];
    const float* log_scale = (const float*)d_in[2];
    const float* bias      = (const float*)d_in[3];
    const float* raw_w     = (const float*)d_in[4];
    const float* raw_h     = (const float*)d_in[5];
    const float* raw_s     = (const float*)d_in[6];
    float* out = (float*)d_out;

    const int D = in_sizes[2];
    const int B = in_sizes[0] / D;

    spline_preproc_kernel<<<D, K64>>>(raw_w, raw_h, raw_s, log_scale);

    dim3 grid(D / DTILE, GRIDY);
    rqs_main_kernel<<<grid, TPB>>>(u, tau, bias, out, B, D);
}